// round 5
// baseline (speedup 1.0000x reference)
#include <cuda_runtime.h>
#include <cstdint>

#define B_    128
#define H_    1024
#define T_    256
#define D_    128
#define PRED_ 96
#define G4    4096

// -------- scratch (static __device__; no allocation allowed) --------
__device__ float g_Xseq[(size_t)T_ * B_ * D_];   // 16 MB  [t][b][d]
__device__ float g_HS0[(size_t)T_ * B_ * H_];    // 128 MB [t][b][h]  layer-0 hidden sequence
__device__ float g_hA[B_ * H_];
__device__ float g_hB[B_ * H_];
__device__ float g_c[B_ * H_];

__device__ __forceinline__ uint32_t f2tf(float f) {
    uint32_t u;
    asm("cvt.rna.tf32.f32 %0, %1;" : "=r"(u) : "f"(f));
    return u;
}
__device__ __forceinline__ float sigf(float x) { return 1.f / (1.f + __expf(-x)); }

// -------- transpose x[b][d][t] -> Xseq[t][b][d] --------
__global__ void k_transpose(const float* __restrict__ x) {
    __shared__ float tile[32][33];
    int b  = blockIdx.z;
    int d0 = blockIdx.x * 32, t0 = blockIdx.y * 32;
    int tx = threadIdx.x, ty = threadIdx.y;
#pragma unroll
    for (int i = 0; i < 32; i += 8)
        tile[ty + i][tx] = x[((size_t)b * D_ + d0 + ty + i) * T_ + t0 + tx];
    __syncthreads();
#pragma unroll
    for (int i = 0; i < 32; i += 8)
        g_Xseq[((size_t)(t0 + ty + i) * B_ + b) * D_ + d0 + tx] = tile[tx][ty + i];
}

__global__ void k_zero() {
    int i = blockIdx.x * blockDim.x + threadIdx.x;
    if (i < B_ * H_) { g_hA[i] = 0.f; g_c[i] = 0.f; }
}

// -------- one LSTM timestep --------
// grid: 128 CTAs, CTA j handles hidden units [8j, 8j+8) -> 32 gate columns.
// block: 256 threads = 8 warps; warp w handles batch rows [16w, 16w+16).
// z = concat(in_t, h_prev) @ W + bias; tf32 mma m16n8k8, fp32 accumulate.
__global__ void __launch_bounds__(256) k_step(
    int layer, int t, int parity,
    const float* __restrict__ W, const float* __restrict__ bias)
{
    const float* A1;
    int K1;
    if (layer == 0) { A1 = g_Xseq + (size_t)t * B_ * D_; K1 = D_; }
    else            { A1 = g_HS0  + (size_t)t * B_ * H_; K1 = H_; }
    const float* hprev = parity ? g_hB : g_hA;
    float*       hnext = parity ? g_hA : g_hB;
    float*       hs    = (layer == 0) ? (g_HS0 + (size_t)t * B_ * H_) : nullptr;

    __shared__ uint32_t As[128 * 33];   // A chunk [128 rows][32 k] padded
    __shared__ uint32_t Ws[32 * 33];    // W chunk [32 k][32 cols] padded

    int tid  = threadIdx.x;
    int warp = tid >> 5, lane = tid & 31;
    int j0 = blockIdx.x * 8;
    int m0 = warp * 16;
    int r = lane >> 2, q = lane & 3;

    float acc[4][4];
#pragma unroll
    for (int g = 0; g < 4; g++)
#pragma unroll
        for (int k = 0; k < 4; k++) acc[g][k] = 0.f;

    int Ktot = K1 + H_;
    for (int kb = 0; kb < Ktot; kb += 32) {
        const float* A; int stride, arow;
        if (kb < K1) { A = A1;    stride = K1; arow = kb; }
        else         { A = hprev; stride = H_; arow = kb - K1; }
        // cooperative loads: A 128x32, W 32x32 (4 gate blocks of 8 cols)
#pragma unroll
        for (int it = 0; it < 16; it++) {
            int idx = tid + it * 256;
            int m = idx >> 5, k = idx & 31;
            As[m * 33 + k] = f2tf(A[(size_t)m * stride + arow + k]);
        }
#pragma unroll
        for (int it = 0; it < 4; it++) {
            int idx = tid + it * 256;
            int k = idx >> 5, cc = idx & 31;
            int col = (cc >> 3) * H_ + j0 + (cc & 7);
            Ws[k * 33 + cc] = f2tf(W[(size_t)(kb + k) * G4 + col]);
        }
        __syncthreads();
#pragma unroll
        for (int kk = 0; kk < 4; kk++) {
            int kbase = kk * 8;
            // mma.m16n8k8.tf32 A-fragment order (CUTLASS SM80 16x8x8 TN):
            //   a0=(r, q)  a1=(r+8, q)  a2=(r, q+4)  a3=(r+8, q+4)
            uint32_t a0 = As[(m0 + r)     * 33 + kbase + q];
            uint32_t a1 = As[(m0 + r + 8) * 33 + kbase + q];
            uint32_t a2 = As[(m0 + r)     * 33 + kbase + q + 4];
            uint32_t a3 = As[(m0 + r + 8) * 33 + kbase + q + 4];
#pragma unroll
            for (int g = 0; g < 4; g++) {
                uint32_t b0 = Ws[(kbase + q)     * 33 + g * 8 + r];
                uint32_t b1 = Ws[(kbase + q + 4) * 33 + g * 8 + r];
                asm volatile(
                    "mma.sync.aligned.m16n8k8.row.col.f32.tf32.tf32.f32 "
                    "{%0,%1,%2,%3}, {%4,%5,%6,%7}, {%8,%9}, {%0,%1,%2,%3};"
                    : "+f"(acc[g][0]), "+f"(acc[g][1]), "+f"(acc[g][2]), "+f"(acc[g][3])
                    : "r"(a0), "r"(a1), "r"(a2), "r"(a3), "r"(b0), "r"(b1));
            }
        }
        __syncthreads();
    }

    // epilogue: gates -> c,h update. reg map: c0:(r,2q) c1:(r,2q+1) c2:(r+8,2q) c3:(r+8,2q+1)
#pragma unroll
    for (int reg = 0; reg < 4; reg++) {
        int b = m0 + r + ((reg & 2) ? 8 : 0);
        int u = q * 2 + (reg & 1);
        int j = j0 + u;
        float zi = acc[0][reg] + bias[j];
        float zf = acc[1][reg] + bias[H_ + j];
        float zo = acc[2][reg] + bias[2 * H_ + j];
        float zg = acc[3][reg] + bias[3 * H_ + j];
        float i_ = sigf(zi), f_ = sigf(zf), o_ = sigf(zo);
        float g_ = tanhf(zg);
        float cn = f_ * g_c[b * H_ + j] + i_ * g_;
        float hn = o_ * tanhf(cn);
        g_c[b * H_ + j]  = cn;
        hnext[b * H_ + j] = hn;
        if (hs) hs[b * H_ + j] = hn;
    }
}

// -------- final FC head: out = tanh(h @ fc_w + fc_b) --------
__global__ void k_fc(int parity, const float* __restrict__ fcw,
                     const float* __restrict__ fcb, float* __restrict__ out) {
    const float* h = parity ? g_hB : g_hA;
    __shared__ float hsh[H_];
    int b = blockIdx.x;
    for (int i = threadIdx.x; i < H_; i += blockDim.x) hsh[i] = h[b * H_ + i];
    __syncthreads();
    for (int p = threadIdx.x; p < PRED_; p += blockDim.x) {
        float s = fcb[p];
#pragma unroll 8
        for (int k = 0; k < H_; k++) s += hsh[k] * fcw[k * PRED_ + p];
        out[b * PRED_ + p] = tanhf(s);
    }
}

__global__ void k_copy(int parity, float* __restrict__ out) {
    const float* h = parity ? g_hB : g_hA;
    int i = blockIdx.x * blockDim.x + threadIdx.x;
    if (i < B_ * H_) {
        out[B_ * PRED_ + i]           = h[i];
        out[B_ * PRED_ + B_ * H_ + i] = g_c[i];
    }
}

extern "C" void kernel_launch(void* const* d_in, const int* in_sizes, int n_in,
                              void* d_out, int out_size) {
    const float* x   = (const float*)d_in[0];
    const float* W0  = (const float*)d_in[1];
    const float* b0  = (const float*)d_in[2];
    const float* W1  = (const float*)d_in[3];
    const float* b1  = (const float*)d_in[4];
    const float* fcw = (const float*)d_in[5];
    const float* fcb = (const float*)d_in[6];
    float* out = (float*)d_out;

    dim3 tg(D_ / 32, T_ / 32, B_);
    k_transpose<<<tg, dim3(32, 8)>>>(x);
    k_zero<<<(B_ * H_ + 255) / 256, 256>>>();

    int par = 0;
    for (int t = 0; t < T_; t++) { k_step<<<128, 256>>>(0, t, par, W0, b0); par ^= 1; }
    for (int t = 0; t < T_; t++) { k_step<<<128, 256>>>(1, t, par, W1, b1); par ^= 1; }

    k_fc<<<B_, 96>>>(par, fcw, fcb, out);
    k_copy<<<(B_ * H_ + 255) / 256, 256>>>(par, out);
}

// round 9
// speedup vs baseline: 1.9596x; 1.9596x over previous
#include <cuda_runtime.h>
#include <cstdint>

#define B_    128
#define H_    1024
#define T_    256
#define D_    128
#define PRED_ 96
#define G4    4096

#define PA 36   // A smem row pad (words): frag bank = (4r+q)&31, bijective
#define PW 40   // W smem row pad (words): frag bank = (8q+r)&31, bijective

// -------- scratch (static __device__; no allocation allowed) --------
__device__ alignas(256) float g_Xseq[(size_t)T_ * B_ * D_];   // 16 MB  [t][b][d]
__device__ alignas(256) float g_HS0[(size_t)T_ * B_ * H_];    // 128 MB [t][b][h]
__device__ alignas(256) float g_hA[B_ * H_];
__device__ alignas(256) float g_hB[B_ * H_];
__device__ alignas(256) float g_c[B_ * H_];

__device__ __forceinline__ uint32_t f2tf(float f) {
    uint32_t u;
    asm("cvt.rna.tf32.f32 %0, %1;" : "=r"(u) : "f"(f));
    return u;
}
__device__ __forceinline__ float sigf(float x) { return 1.f / (1.f + __expf(-x)); }

// -------- transpose x[b][d][t] -> Xseq[t][b][d] --------
__global__ void k_transpose(const float* __restrict__ x) {
    __shared__ float tile[32][33];
    int b  = blockIdx.z;
    int d0 = blockIdx.x * 32, t0 = blockIdx.y * 32;
    int tx = threadIdx.x, ty = threadIdx.y;
#pragma unroll
    for (int i = 0; i < 32; i += 8)
        tile[ty + i][tx] = x[((size_t)b * D_ + d0 + ty + i) * T_ + t0 + tx];
    __syncthreads();
#pragma unroll
    for (int i = 0; i < 32; i += 8)
        g_Xseq[((size_t)(t0 + ty + i) * B_ + b) * D_ + d0 + tx] = tile[tx][ty + i];
}

__global__ void k_zero() {
    int i = blockIdx.x * blockDim.x + threadIdx.x;
    if (i < B_ * H_) { g_hA[i] = 0.f; g_c[i] = 0.f; }
}

// -------- one LSTM timestep, software-pipelined --------
// grid: 128 CTAs, CTA j: hidden units [8j,8j+8) -> 32 gate cols (4 gates x 8).
// block: 256 threads = 8 warps; warp w: batch rows [16w,16w+16).
// Pipeline: regs(chunk k+1) prefetched during MMA(chunk k); 1 barrier/chunk.
__global__ void __launch_bounds__(256) k_step(
    int layer, int t, int parity,
    const float* __restrict__ W, const float* __restrict__ bias)
{
    const float* A1;
    int K1;
    if (layer == 0) { A1 = g_Xseq + (size_t)t * B_ * D_; K1 = D_; }
    else            { A1 = g_HS0  + (size_t)t * B_ * H_; K1 = H_; }
    const float* hprev = parity ? g_hB : g_hA;
    float*       hnext = parity ? g_hA : g_hB;
    float*       hs    = (layer == 0) ? (g_HS0 + (size_t)t * B_ * H_) : nullptr;

    __shared__ alignas(16) uint32_t As[2][128 * PA];  // 36.9 KB
    __shared__ alignas(16) uint32_t Ws[2][32 * PW];   // 10.2 KB

    const int tid  = threadIdx.x;
    const int warp = tid >> 5, lane = tid & 31;
    const int j0 = blockIdx.x * 8;
    const int m0 = warp * 16;
    const int r = lane >> 2, q = lane & 3;

    // prefetch-register mapping
    const int am = tid >> 1;            // A row 0..127
    const int ak = (tid & 1) * 16;      // A k-offset 0 or 16
    const int wk = tid >> 3;            // W k-row 0..31
    const int wc = tid & 7;             // W col-in-gate 0..7

    float4 pa[4];
    float  pw[4];

    float acc[4][4];
#pragma unroll
    for (int g = 0; g < 4; g++)
#pragma unroll
        for (int k = 0; k < 4; k++) acc[g][k] = 0.f;

    const int Ktot = K1 + H_;

    // ---- prefetch chunk 0 ----
    {
        const float* A = A1; int stride = K1, arow = 0;          // kb=0 < K1 always
        const float* src = A + (size_t)am * stride + arow + ak;
#pragma unroll
        for (int j = 0; j < 4; j++) pa[j] = *(const float4*)(src + j * 4);
#pragma unroll
        for (int g = 0; g < 4; g++)
            pw[g] = W[(size_t)wk * G4 + g * H_ + j0 + wc];
    }

    int buf = 0;
    for (int kb = 0; kb < Ktot; kb += 32, buf ^= 1) {
        // ---- store prefetched regs -> smem[buf] ----
        {
            uint32_t* dst = &As[buf][am * PA + ak];
#pragma unroll
            for (int j = 0; j < 4; j++) {
                uint4 u;
                u.x = f2tf(pa[j].x); u.y = f2tf(pa[j].y);
                u.z = f2tf(pa[j].z); u.w = f2tf(pa[j].w);
                *(uint4*)(dst + j * 4) = u;
            }
#pragma unroll
            for (int g = 0; g < 4; g++)
                Ws[buf][wk * PW + g * 8 + wc] = f2tf(pw[g]);
        }
        __syncthreads();

        // ---- prefetch chunk kb+32 (overlaps with MMA below) ----
        if (kb + 32 < Ktot) {
            int kn = kb + 32;
            const float* A; int stride, arow;
            if (kn < K1) { A = A1;    stride = K1; arow = kn; }
            else         { A = hprev; stride = H_; arow = kn - K1; }
            const float* src = A + (size_t)am * stride + arow + ak;
#pragma unroll
            for (int j = 0; j < 4; j++) pa[j] = *(const float4*)(src + j * 4);
#pragma unroll
            for (int g = 0; g < 4; g++)
                pw[g] = W[(size_t)(kn + wk) * G4 + g * H_ + j0 + wc];
        }

        // ---- MMA on smem[buf] ----
        const uint32_t* as = As[buf];
        const uint32_t* ws = Ws[buf];
#pragma unroll
        for (int kk = 0; kk < 4; kk++) {
            int kbase = kk * 8;
            // m16n8k8 tf32 A frag: a0=(r,q) a1=(r+8,q) a2=(r,q+4) a3=(r+8,q+4)
            uint32_t a0 = as[(m0 + r)     * PA + kbase + q];
            uint32_t a1 = as[(m0 + r + 8) * PA + kbase + q];
            uint32_t a2 = as[(m0 + r)     * PA + kbase + q + 4];
            uint32_t a3 = as[(m0 + r + 8) * PA + kbase + q + 4];
#pragma unroll
            for (int g = 0; g < 4; g++) {
                uint32_t b0 = ws[(kbase + q)     * PW + g * 8 + r];
                uint32_t b1 = ws[(kbase + q + 4) * PW + g * 8 + r];
                asm volatile(
                    "mma.sync.aligned.m16n8k8.row.col.f32.tf32.tf32.f32 "
                    "{%0,%1,%2,%3}, {%4,%5,%6,%7}, {%8,%9}, {%0,%1,%2,%3};"
                    : "+f"(acc[g][0]), "+f"(acc[g][1]), "+f"(acc[g][2]), "+f"(acc[g][3])
                    : "r"(a0), "r"(a1), "r"(a2), "r"(a3), "r"(b0), "r"(b1));
            }
        }
        // no second barrier needed: next store targets buf^1, whose last MMA
        // readers finished before the sync this warp already passed.
    }

    // epilogue: c0:(r,2q) c1:(r,2q+1) c2:(r+8,2q) c3:(r+8,2q+1)
#pragma unroll
    for (int reg = 0; reg < 4; reg++) {
        int b = m0 + r + ((reg & 2) ? 8 : 0);
        int u = q * 2 + (reg & 1);
        int j = j0 + u;
        float zi = acc[0][reg] + bias[j];
        float zf = acc[1][reg] + bias[H_ + j];
        float zo = acc[2][reg] + bias[2 * H_ + j];
        float zg = acc[3][reg] + bias[3 * H_ + j];
        float i_ = sigf(zi), f_ = sigf(zf), o_ = sigf(zo);
        float g_ = tanhf(zg);
        float cn = f_ * g_c[b * H_ + j] + i_ * g_;
        float hn = o_ * tanhf(cn);
        g_c[b * H_ + j]  = cn;
        hnext[b * H_ + j] = hn;
        if (hs) hs[b * H_ + j] = hn;
    }
}

// -------- final FC head: out = tanh(h @ fc_w + fc_b) --------
__global__ void k_fc(int parity, const float* __restrict__ fcw,
                     const float* __restrict__ fcb, float* __restrict__ out) {
    const float* h = parity ? g_hB : g_hA;
    __shared__ float hsh[H_];
    int b = blockIdx.x;
    for (int i = threadIdx.x; i < H_; i += blockDim.x) hsh[i] = h[b * H_ + i];
    __syncthreads();
    for (int p = threadIdx.x; p < PRED_; p += blockDim.x) {
        float s = fcb[p];
#pragma unroll 8
        for (int k = 0; k < H_; k++) s += hsh[k] * fcw[k * PRED_ + p];
        out[b * PRED_ + p] = tanhf(s);
    }
}

__global__ void k_copy(int parity, float* __restrict__ out) {
    const float* h = parity ? g_hB : g_hA;
    int i = blockIdx.x * blockDim.x + threadIdx.x;
    if (i < B_ * H_) {
        out[B_ * PRED_ + i]           = h[i];
        out[B_ * PRED_ + B_ * H_ + i] = g_c[i];
    }
}

extern "C" void kernel_launch(void* const* d_in, const int* in_sizes, int n_in,
                              void* d_out, int out_size) {
    const float* x   = (const float*)d_in[0];
    const float* W0  = (const float*)d_in[1];
    const float* b0  = (const float*)d_in[2];
    const float* W1  = (const float*)d_in[3];
    const float* b1  = (const float*)d_in[4];
    const float* fcw = (const float*)d_in[5];
    const float* fcb = (const float*)d_in[6];
    float* out = (float*)d_out;

    dim3 tg(D_ / 32, T_ / 32, B_);
    k_transpose<<<tg, dim3(32, 8)>>>(x);
    k_zero<<<(B_ * H_ + 255) / 256, 256>>>();

    int par = 0;
    for (int t = 0; t < T_; t++) { k_step<<<128, 256>>>(0, t, par, W0, b0); par ^= 1; }
    for (int t = 0; t < T_; t++) { k_step<<<128, 256>>>(1, t, par, W1, b1); par ^= 1; }

    k_fc<<<B_, 96>>>(par, fcw, fcb, out);
    k_copy<<<(B_ * H_ + 255) / 256, 256>>>(par, out);
}

// round 11
// speedup vs baseline: 2.1383x; 1.0912x over previous
#include <cuda_runtime.h>
#include <cstdint>

#define B_    128
#define H_    1024
#define T_    256
#define D_    128
#define PRED_ 96
#define G4    4096

#define PA 36   // A smem row pad (words): frag bank = (4r+q)&31, bijective
#define PW 40   // W smem row pad (words): frag bank = (8q+r)&31, bijective

// dynamic smem: As[2 groups][2 bufs][128*PA] + Ws[2][2][32*PW]
#define AS_WORDS (128 * PA)                 // 4608
#define WS_WORDS (32 * PW)                  // 1280
#define SMEM_WORDS (2 * 2 * AS_WORDS + 2 * 2 * WS_WORDS)
#define SMEM_BYTES (SMEM_WORDS * 4)        // 94208 B

// -------- scratch (static __device__; no allocation allowed) --------
__device__ alignas(256) float g_Xseq[(size_t)T_ * B_ * D_];   // 16 MB  [t][b][d]
__device__ alignas(256) float g_HS0[(size_t)T_ * B_ * H_];    // 128 MB [t][b][h]
__device__ alignas(256) float g_hA[B_ * H_];
__device__ alignas(256) float g_hB[B_ * H_];
__device__ alignas(256) float g_c[B_ * H_];

__device__ __forceinline__ uint32_t f2tf(float f) {
    uint32_t u;
    asm("cvt.rna.tf32.f32 %0, %1;" : "=r"(u) : "f"(f));
    return u;
}
__device__ __forceinline__ float sigf(float x) { return 1.f / (1.f + __expf(-x)); }
__device__ __forceinline__ void barg(int id) {
    asm volatile("bar.sync %0, %1;" :: "r"(id), "r"(256) : "memory");
}

// -------- transpose x[b][d][t] -> Xseq[t][b][d] --------
__global__ void k_transpose(const float* __restrict__ x) {
    __shared__ float tile[32][33];
    int b  = blockIdx.z;
    int d0 = blockIdx.x * 32, t0 = blockIdx.y * 32;
    int tx = threadIdx.x, ty = threadIdx.y;
#pragma unroll
    for (int i = 0; i < 32; i += 8)
        tile[ty + i][tx] = x[((size_t)b * D_ + d0 + ty + i) * T_ + t0 + tx];
    __syncthreads();
#pragma unroll
    for (int i = 0; i < 32; i += 8)
        g_Xseq[((size_t)(t0 + ty + i) * B_ + b) * D_ + d0 + tx] = tile[tx][ty + i];
}

__global__ void k_zero() {
    int i = blockIdx.x * blockDim.x + threadIdx.x;
    if (i < B_ * H_) { g_hA[i] = 0.f; g_c[i] = 0.f; }
}

// -------- one LSTM timestep: 512 threads, K split across 2 warpgroups --------
// grid: 128 CTAs, CTA j: hidden units [8j,8j+8) -> 32 gate cols (4 gates x 8).
// group g = tid>>8 handles K-half g with its own double-buffered smem + named
// barrier; partials reduced via smem, group 0 does the gate epilogue.
__global__ void __launch_bounds__(512) k_step(
    int layer, int t, int parity,
    const float* __restrict__ W, const float* __restrict__ bias)
{
    const float* A1;
    int K1;
    if (layer == 0) { A1 = g_Xseq + (size_t)t * B_ * D_; K1 = D_; }
    else            { A1 = g_HS0  + (size_t)t * B_ * H_; K1 = H_; }
    const float* hprev = parity ? g_hB : g_hA;
    float*       hnext = parity ? g_hA : g_hB;
    float*       hs    = (layer == 0) ? (g_HS0 + (size_t)t * B_ * H_) : nullptr;

    extern __shared__ uint32_t smem[];

    const int tid   = threadIdx.x;
    const int group = tid >> 8;          // 0 or 1
    const int gtid  = tid & 255;
    const int warp  = gtid >> 5, lane = gtid & 31;
    const int j0 = blockIdx.x * 8;
    const int m0 = warp * 16;
    const int r = lane >> 2, q = lane & 3;

    uint32_t* AsG = smem + group * (2 * AS_WORDS);
    uint32_t* WsG = smem + 4 * AS_WORDS + group * (2 * WS_WORDS);
    float*    red = (float*)(smem + 2 * AS_WORDS);   // aliases group1's As

    // prefetch-register mapping (within group)
    const int am = gtid >> 1;            // A row 0..127
    const int ak = (gtid & 1) * 16;      // A k-offset 0 or 16
    const int wk = gtid >> 3;            // W k-row 0..31
    const int wc = gtid & 7;             // W col-in-gate 0..7

    float4 pa[4];
    float  pw[4];

    float acc[4][4];
#pragma unroll
    for (int g = 0; g < 4; g++)
#pragma unroll
        for (int k = 0; k < 4; k++) acc[g][k] = 0.f;

    const int Ktot   = K1 + H_;
    const int Khalf  = Ktot >> 1;                 // chunk(32)-aligned for both layers
    const int kstart = group * Khalf;
    const int kend   = kstart + Khalf;
    const int barid  = 1 + group;

    // ---- prefetch first chunk of this group's range ----
    {
        int kn = kstart;
        const float* A; int stride, arow;
        if (kn < K1) { A = A1;    stride = K1; arow = kn; }
        else         { A = hprev; stride = H_; arow = kn - K1; }
        const float* src = A + (size_t)am * stride + arow + ak;
#pragma unroll
        for (int j = 0; j < 4; j++) pa[j] = *(const float4*)(src + j * 4);
#pragma unroll
        for (int g = 0; g < 4; g++)
            pw[g] = W[(size_t)(kn + wk) * G4 + g * H_ + j0 + wc];
    }

    int buf = 0;
    for (int kb = kstart; kb < kend; kb += 32, buf ^= 1) {
        // ---- store prefetched regs -> smem[group][buf] ----
        {
            uint32_t* dst = AsG + buf * AS_WORDS + am * PA + ak;
#pragma unroll
            for (int j = 0; j < 4; j++) {
                uint4 u;
                u.x = f2tf(pa[j].x); u.y = f2tf(pa[j].y);
                u.z = f2tf(pa[j].z); u.w = f2tf(pa[j].w);
                *(uint4*)(dst + j * 4) = u;
            }
            uint32_t* wdst = WsG + buf * WS_WORDS;
#pragma unroll
            for (int g = 0; g < 4; g++)
                wdst[wk * PW + g * 8 + wc] = f2tf(pw[g]);
        }
        barg(barid);

        // ---- prefetch next chunk (overlaps MMA) ----
        if (kb + 32 < kend) {
            int kn = kb + 32;
            const float* A; int stride, arow;
            if (kn < K1) { A = A1;    stride = K1; arow = kn; }
            else         { A = hprev; stride = H_; arow = kn - K1; }
            const float* src = A + (size_t)am * stride + arow + ak;
#pragma unroll
            for (int j = 0; j < 4; j++) pa[j] = *(const float4*)(src + j * 4);
#pragma unroll
            for (int g = 0; g < 4; g++)
                pw[g] = W[(size_t)(kn + wk) * G4 + g * H_ + j0 + wc];
        }

        // ---- MMA on smem[group][buf] ----
        const uint32_t* as = AsG + buf * AS_WORDS;
        const uint32_t* ws = WsG + buf * WS_WORDS;
#pragma unroll
        for (int kk = 0; kk < 4; kk++) {
            int kbase = kk * 8;
            // m16n8k8 tf32 A frag: a0=(r,q) a1=(r+8,q) a2=(r,q+4) a3=(r+8,q+4)
            uint32_t a0 = as[(m0 + r)     * PA + kbase + q];
            uint32_t a1 = as[(m0 + r + 8) * PA + kbase + q];
            uint32_t a2 = as[(m0 + r)     * PA + kbase + q + 4];
            uint32_t a3 = as[(m0 + r + 8) * PA + kbase + q + 4];
#pragma unroll
            for (int g = 0; g < 4; g++) {
                uint32_t b0 = ws[(kbase + q)     * PW + g * 8 + r];
                uint32_t b1 = ws[(kbase + q + 4) * PW + g * 8 + r];
                asm volatile(
                    "mma.sync.aligned.m16n8k8.row.col.f32.tf32.tf32.f32 "
                    "{%0,%1,%2,%3}, {%4,%5,%6,%7}, {%8,%9}, {%0,%1,%2,%3};"
                    : "+f"(acc[g][0]), "+f"(acc[g][1]), "+f"(acc[g][2]), "+f"(acc[g][3])
                    : "r"(a0), "r"(a1), "r"(a2), "r"(a3), "r"(b0), "r"(b1));
            }
        }
        // no trailing barrier: double buffer + head barrier make it redundant
    }

    // ---- cross-group reduction: group1 partials -> smem, group0 adds ----
    if (group == 1) {
        barg(2);   // all group-1 MMA reads of group-1 smem done before overwrite
#pragma unroll
        for (int g = 0; g < 4; g++)
#pragma unroll
            for (int k = 0; k < 4; k++)
                red[gtid * 16 + g * 4 + k] = acc[g][k];
    }
    __syncthreads();
    if (group == 0) {
#pragma unroll
        for (int g = 0; g < 4; g++)
#pragma unroll
            for (int k = 0; k < 4; k++)
                acc[g][k] += red[gtid * 16 + g * 4 + k];

        // epilogue: c0:(r,2q) c1:(r,2q+1) c2:(r+8,2q) c3:(r+8,2q+1)
#pragma unroll
        for (int reg = 0; reg < 4; reg++) {
            int b = m0 + r + ((reg & 2) ? 8 : 0);
            int u = q * 2 + (reg & 1);
            int j = j0 + u;
            float zi = acc[0][reg] + bias[j];
            float zf = acc[1][reg] + bias[H_ + j];
            float zo = acc[2][reg] + bias[2 * H_ + j];
            float zg = acc[3][reg] + bias[3 * H_ + j];
            float i_ = sigf(zi), f_ = sigf(zf), o_ = sigf(zo);
            float g_ = tanhf(zg);
            float cn = f_ * g_c[b * H_ + j] + i_ * g_;
            float hn = o_ * tanhf(cn);
            g_c[b * H_ + j]  = cn;
            hnext[b * H_ + j] = hn;
            if (hs) hs[b * H_ + j] = hn;
        }
    }
}

// -------- final FC head: out = tanh(h @ fc_w + fc_b) --------
__global__ void k_fc(int parity, const float* __restrict__ fcw,
                     const float* __restrict__ fcb, float* __restrict__ out) {
    const float* h = parity ? g_hB : g_hA;
    __shared__ float hsh[H_];
    int b = blockIdx.x;
    for (int i = threadIdx.x; i < H_; i += blockDim.x) hsh[i] = h[b * H_ + i];
    __syncthreads();
    for (int p = threadIdx.x; p < PRED_; p += blockDim.x) {
        float s = fcb[p];
#pragma unroll 8
        for (int k = 0; k < H_; k++) s += hsh[k] * fcw[k * PRED_ + p];
        out[b * PRED_ + p] = tanhf(s);
    }
}

__global__ void k_copy(int parity, float* __restrict__ out) {
    const float* h = parity ? g_hB : g_hA;
    int i = blockIdx.x * blockDim.x + threadIdx.x;
    if (i < B_ * H_) {
        out[B_ * PRED_ + i]           = h[i];
        out[B_ * PRED_ + B_ * H_ + i] = g_c[i];
    }
}

extern "C" void kernel_launch(void* const* d_in, const int* in_sizes, int n_in,
                              void* d_out, int out_size) {
    const float* x   = (const float*)d_in[0];
    const float* W0  = (const float*)d_in[1];
    const float* b0  = (const float*)d_in[2];
    const float* W1  = (const float*)d_in[3];
    const float* b1  = (const float*)d_in[4];
    const float* fcw = (const float*)d_in[5];
    const float* fcb = (const float*)d_in[6];
    float* out = (float*)d_out;

    cudaFuncSetAttribute(k_step, cudaFuncAttributeMaxDynamicSharedMemorySize,
                         SMEM_BYTES);

    dim3 tg(D_ / 32, T_ / 32, B_);
    k_transpose<<<tg, dim3(32, 8)>>>(x);
    k_zero<<<(B_ * H_ + 255) / 256, 256>>>();

    int par = 0;
    for (int t = 0; t < T_; t++) { k_step<<<128, 512, SMEM_BYTES>>>(0, t, par, W0, b0); par ^= 1; }
    for (int t = 0; t < T_; t++) { k_step<<<128, 512, SMEM_BYTES>>>(1, t, par, W1, b1); par ^= 1; }

    k_fc<<<B_, 96>>>(par, fcw, fcb, out);
    k_copy<<<(B_ * H_ + 255) / 256, 256>>>(par, out);
}

// round 12
// speedup vs baseline: 2.7441x; 1.2833x over previous
#include <cuda_runtime.h>
#include <cstdint>
#include <cuda_fp16.h>

#define B_    128
#define H_    1024
#define T_    256
#define D_    128
#define PRED_ 96
#define G4    4096

// ---- smem geometry ----
#define PA2       20                    // A row pitch (uint32 half2 units): 16 kp + 4 pad
#define AS2_WORDS (128 * PA2)           // 2560 words per A buffer
#define W_OFF     (4 * AS2_WORDS)       // A region: [2 groups][2 bufs]
#define PKP1      1028                  // W col pitch (kp units), 1028 % 32 == 4
#define PKP0      580                   // 580 % 32 == 4
#define SMEM_WORDS_MAX (W_OFF + 32 * PKP1)     // 43136 words
#define SMEM_BYTES_MAX (SMEM_WORDS_MAX * 4)    // 172544 B

// -------- scratch (static __device__; no allocation allowed) --------
__device__ alignas(256) float g_Xseq[(size_t)T_ * B_ * D_];   // [t][b][d]
__device__ alignas(256) float g_HS0[(size_t)T_ * B_ * H_];    // [t][b][h]
__device__ alignas(256) float g_hA[B_ * H_];
__device__ alignas(256) float g_hB[B_ * H_];
__device__ alignas(256) float g_c[B_ * H_];
__device__ unsigned g_barcnt;

__device__ __forceinline__ uint32_t f2h2(float a, float b) {
    __half2 h = __floats2half2_rn(a, b);      // .x = a (low 16) = even k
    return *(uint32_t*)&h;
}
__device__ __forceinline__ float sigf(float x) { return 1.f / (1.f + __expf(-x)); }
__device__ __forceinline__ void barg(int id) {
    asm volatile("bar.sync %0, %1;" :: "r"(id), "r"(256) : "memory");
}
__device__ __forceinline__ float4 ldcg4(const float* p) {
    float4 v;
    asm volatile("ld.global.cg.v4.f32 {%0,%1,%2,%3}, [%4];"
                 : "=f"(v.x), "=f"(v.y), "=f"(v.z), "=f"(v.w) : "l"(p));
    return v;
}

// -------- transpose x[b][d][t] -> Xseq[t][b][d] --------
__global__ void k_transpose(const float* __restrict__ x) {
    __shared__ float tile[32][33];
    int b  = blockIdx.z;
    int d0 = blockIdx.x * 32, t0 = blockIdx.y * 32;
    int tx = threadIdx.x, ty = threadIdx.y;
#pragma unroll
    for (int i = 0; i < 32; i += 8)
        tile[ty + i][tx] = x[((size_t)b * D_ + d0 + ty + i) * T_ + t0 + tx];
    __syncthreads();
#pragma unroll
    for (int i = 0; i < 32; i += 8)
        g_Xseq[((size_t)(t0 + ty + i) * B_ + b) * D_ + d0 + tx] = tile[tx][ty + i];
}

__global__ void k_zero() {
    int i = blockIdx.x * blockDim.x + threadIdx.x;
    if (i < B_ * H_) { g_hA[i] = 0.f; g_c[i] = 0.f; }
    if (i == 0) g_barcnt = 0u;
}

// -------- persistent per-layer LSTM kernel --------
// grid 128 CTAs (1/SM, all co-resident), block 512 = 2 groups x 8 warps.
// CTA j: hidden units [8j,8j+8) -> 32 gate cols. group g: K-half g.
// W slice resident in smem as fp16 (col-major, pitch PKP). Loop over T steps
// with a global spin barrier between steps (release: fence+atomicAdd;
// acquire: poll + fence; h loads via ld.cg to bypass non-coherent L1).
__global__ void __launch_bounds__(512) k_layer(
    int layer, int tbase,
    const float* __restrict__ W, const float* __restrict__ bias)
{
    const int K1   = layer ? H_ : D_;
    const int Ktot = K1 + H_;
    const int PKP  = layer ? PKP1 : PKP0;

    extern __shared__ uint32_t smem[];
    uint32_t* As  = smem;                 // [group][buf][AS2_WORDS]
    uint32_t* Wsm = smem + W_OFF;         // [32 cols][PKP kp]
    float*    red = (float*)(smem + 2 * AS2_WORDS);   // aliases group1 A bufs

    const int tid   = threadIdx.x;
    const int group = tid >> 8;
    const int gtid  = tid & 255;
    const int warp  = gtid >> 5, lane = gtid & 31;
    const int j0 = blockIdx.x * 8;
    const int m0 = warp * 16;
    const int r = lane >> 2, q = lane & 3;

    // ---- load W slice into smem (once) ----
    {
        const int kpRows = Ktot >> 1;
        for (int idx = tid; idx < kpRows * 32; idx += 512) {
            int kp = idx >> 5, cl = idx & 31;
            int gcol = (cl >> 3) * H_ + j0 + (cl & 7);
            float w0 = W[(size_t)(2 * kp)     * G4 + gcol];
            float w1 = W[(size_t)(2 * kp + 1) * G4 + gcol];
            Wsm[cl * PKP + kp] = f2h2(w0, w1);
        }
    }
    __syncthreads();

    // prefetch-register mapping (within group)
    const int am  = gtid >> 1;           // A row 0..127
    const int akp = (gtid & 1) * 8;      // kp offset in row (k offset = 2*akp)
    const int Khalf  = Ktot >> 1;
    const int kstart = group * Khalf;
    const int kend   = kstart + Khalf;
    const int barid  = 1 + group;

    for (int t = 0; t < T_; t++) {
        const int par = t & 1;
        const float* A1    = layer ? (g_HS0 + (size_t)t * B_ * H_)
                                   : (g_Xseq + (size_t)t * B_ * D_);
        const float* hprev = par ? g_hB : g_hA;
        float*       hnext = par ? g_hA : g_hB;
        float*       hs    = layer ? nullptr : (g_HS0 + (size_t)t * B_ * H_);

        float acc[4][4];
#pragma unroll
        for (int g = 0; g < 4; g++)
#pragma unroll
            for (int k = 0; k < 4; k++) acc[g][k] = 0.f;

        float4 pa[4];
        // ---- prefetch first chunk of this group's K-range ----
        {
            int kn = kstart;
            const float* A; int stride, arow;
            if (kn < K1) { A = A1;    stride = K1; arow = kn; }
            else         { A = hprev; stride = H_; arow = kn - K1; }
            const float* src = A + (size_t)am * stride + arow + 2 * akp;
#pragma unroll
            for (int j = 0; j < 4; j++) pa[j] = ldcg4(src + j * 4);
        }

        int buf = 0;
        for (int kb = kstart; kb < kend; kb += 32, buf ^= 1) {
            // ---- store prefetched A -> smem[group][buf] (fp16 pairs) ----
            {
                uint32_t* dst = As + group * (2 * AS2_WORDS) + buf * AS2_WORDS
                                   + am * PA2 + akp;
                uint4 u0, u1;
                u0.x = f2h2(pa[0].x, pa[0].y); u0.y = f2h2(pa[0].z, pa[0].w);
                u0.z = f2h2(pa[1].x, pa[1].y); u0.w = f2h2(pa[1].z, pa[1].w);
                u1.x = f2h2(pa[2].x, pa[2].y); u1.y = f2h2(pa[2].z, pa[2].w);
                u1.z = f2h2(pa[3].x, pa[3].y); u1.w = f2h2(pa[3].z, pa[3].w);
                *(uint4*)(dst)     = u0;
                *(uint4*)(dst + 4) = u1;
            }
            barg(barid);

            // ---- prefetch next chunk (overlaps MMA) ----
            if (kb + 32 < kend) {
                int kn = kb + 32;
                const float* A; int stride, arow;
                if (kn < K1) { A = A1;    stride = K1; arow = kn; }
                else         { A = hprev; stride = H_; arow = kn - K1; }
                const float* src = A + (size_t)am * stride + arow + 2 * akp;
#pragma unroll
                for (int j = 0; j < 4; j++) pa[j] = ldcg4(src + j * 4);
            }

            // ---- MMA: A from smem buf, B(W) from resident smem ----
            const uint32_t* as = As + group * (2 * AS2_WORDS) + buf * AS2_WORDS;
            const int kpg = kb >> 1;
#pragma unroll
            for (int ks = 0; ks < 2; ks++) {
                const int kpb = ks * 8;
                // m16n8k16 f16 A frag: a0=(r,2q) a1=(r+8,2q) a2=(r,2q+8) a3=(r+8,2q+8)
                uint32_t a0 = as[(m0 + r)     * PA2 + kpb + q];
                uint32_t a1 = as[(m0 + r + 8) * PA2 + kpb + q];
                uint32_t a2 = as[(m0 + r)     * PA2 + kpb + q + 4];
                uint32_t a3 = as[(m0 + r + 8) * PA2 + kpb + q + 4];
#pragma unroll
                for (int g = 0; g < 4; g++) {
                    const uint32_t* wr = Wsm + (g * 8 + r) * PKP + kpg + kpb;
                    uint32_t b0 = wr[q];
                    uint32_t b1 = wr[q + 4];
                    asm volatile(
                        "mma.sync.aligned.m16n8k16.row.col.f32.f16.f16.f32 "
                        "{%0,%1,%2,%3}, {%4,%5,%6,%7}, {%8,%9}, {%0,%1,%2,%3};"
                        : "+f"(acc[g][0]), "+f"(acc[g][1]),
                          "+f"(acc[g][2]), "+f"(acc[g][3])
                        : "r"(a0), "r"(a1), "r"(a2), "r"(a3), "r"(b0), "r"(b1));
                }
            }
        }

        // ---- cross-group reduction ----
        if (group == 1) {
            barg(2);   // all group-1 reads of group-1 A bufs done before aliasing
#pragma unroll
            for (int g = 0; g < 4; g++)
#pragma unroll
                for (int k = 0; k < 4; k++)
                    red[gtid * 16 + g * 4 + k] = acc[g][k];
        }
        __syncthreads();
        if (group == 0) {
#pragma unroll
            for (int g = 0; g < 4; g++)
#pragma unroll
                for (int k = 0; k < 4; k++)
                    acc[g][k] += red[gtid * 16 + g * 4 + k];

            // epilogue: c0:(r,2q) c1:(r,2q+1) c2:(r+8,2q) c3:(r+8,2q+1)
#pragma unroll
            for (int reg = 0; reg < 4; reg++) {
                int b = m0 + r + ((reg & 2) ? 8 : 0);
                int u = q * 2 + (reg & 1);
                int j = j0 + u;
                float zi = acc[0][reg] + bias[j];
                float zf = acc[1][reg] + bias[H_ + j];
                float zo = acc[2][reg] + bias[2 * H_ + j];
                float zg = acc[3][reg] + bias[3 * H_ + j];
                float i_ = sigf(zi), f_ = sigf(zf), o_ = sigf(zo);
                float g_ = tanhf(zg);
                float cn = f_ * g_c[b * H_ + j] + i_ * g_;
                float hn = o_ * tanhf(cn);
                g_c[b * H_ + j]   = cn;
                hnext[b * H_ + j] = hn;
                if (hs) hs[b * H_ + j] = hn;
            }
        }

        // ---- global barrier: release h stores, then wait for all CTAs ----
        __threadfence();
        __syncthreads();
        if (tid == 0) {
            atomicAdd(&g_barcnt, 1u);
            unsigned target = 128u * (unsigned)(tbase + t + 1);
            while (*(volatile unsigned*)&g_barcnt < target) __nanosleep(64);
            __threadfence();
        }
        __syncthreads();
    }
}

// -------- final FC head: out = tanh(h @ fc_w + fc_b) --------
__global__ void k_fc(int parity, const float* __restrict__ fcw,
                     const float* __restrict__ fcb, float* __restrict__ out) {
    const float* h = parity ? g_hB : g_hA;
    __shared__ float hsh[H_];
    int b = blockIdx.x;
    for (int i = threadIdx.x; i < H_; i += blockDim.x) hsh[i] = h[b * H_ + i];
    __syncthreads();
    for (int p = threadIdx.x; p < PRED_; p += blockDim.x) {
        float s = fcb[p];
#pragma unroll 8
        for (int k = 0; k < H_; k++) s += hsh[k] * fcw[k * PRED_ + p];
        out[b * PRED_ + p] = tanhf(s);
    }
}

__global__ void k_copy(int parity, float* __restrict__ out) {
    const float* h = parity ? g_hB : g_hA;
    int i = blockIdx.x * blockDim.x + threadIdx.x;
    if (i < B_ * H_) {
        out[B_ * PRED_ + i]           = h[i];
        out[B_ * PRED_ + B_ * H_ + i] = g_c[i];
    }
}

extern "C" void kernel_launch(void* const* d_in, const int* in_sizes, int n_in,
                              void* d_out, int out_size) {
    const float* x   = (const float*)d_in[0];
    const float* W0  = (const float*)d_in[1];
    const float* b0  = (const float*)d_in[2];
    const float* W1  = (const float*)d_in[3];
    const float* b1  = (const float*)d_in[4];
    const float* fcw = (const float*)d_in[5];
    const float* fcb = (const float*)d_in[6];
    float* out = (float*)d_out;

    cudaFuncSetAttribute(k_layer, cudaFuncAttributeMaxDynamicSharedMemorySize,
                         SMEM_BYTES_MAX);

    dim3 tg(D_ / 32, T_ / 32, B_);
    k_transpose<<<tg, dim3(32, 8)>>>(x);
    k_zero<<<(B_ * H_ + 255) / 256, 256>>>();

    // 512 steps total; parity at step s is s&1, final parity = 0
    k_layer<<<128, 512, SMEM_BYTES_MAX>>>(0, 0,  W0, b0);
    k_layer<<<128, 512, SMEM_BYTES_MAX>>>(1, T_, W1, b1);

    k_fc<<<B_, 96>>>(0, fcw, fcb, out);
    k_copy<<<(B_ * H_ + 255) / 256, 256>>>(0, out);
}